// round 1
// baseline (speedup 1.0000x reference)
#include <cuda_runtime.h>
#include <math.h>
#include <stdint.h>

// Problem constants
#define DMODEL 512
#define NHEADS 8
#define HDIM   64
#define NEXP   8
#define DFF    1024
#define BATCH  8
#define NCHUNK 256
#define NTOT   768            // 3 * 256
#define TOK    (BATCH * NTOT) // 6144
#define SLOTS  (TOK * 2)      // 12288 routed (token, slot) rows

// ---------------- scratch (static device allocations are allowed) ----------
__device__ float g_h  [TOK * DMODEL];    // LN1 output
__device__ float g_q  [TOK * DMODEL];    // [bh][n][hd]
__device__ float g_k  [TOK * DMODEL];
__device__ float g_v  [TOK * DMODEL];
__device__ float g_o  [TOK * DMODEL];    // attn out, [token][h*64+hd]
__device__ float g_x2 [TOK * DMODEL];    // 2*(o@proj + b)
__device__ float g_hn [TOK * DMODEL];    // LN2 output
__device__ float g_hid[SLOTS * DFF];     // gelu(hn @ w1 + b1), by slot entry
__device__ float g_comb[SLOTS * DMODEL]; // conf * (hid @ w2 + b2), by slot entry
__device__ int   g_rows[NEXP * SLOTS];   // per-expert slot-entry lists
__device__ int   g_cnt [NEXP];
__device__ float g_conf[SLOTS];

// ---------------- helpers ---------------------------------------------------
__device__ __forceinline__ void blockReduce2(float& a, float& b, float* sm) {
    #pragma unroll
    for (int o = 16; o; o >>= 1) {
        a += __shfl_down_sync(0xffffffffu, a, o);
        b += __shfl_down_sync(0xffffffffu, b, o);
    }
    int w = threadIdx.x >> 5, l = threadIdx.x & 31;
    int nw = blockDim.x >> 5;
    if (l == 0) { sm[w] = a; sm[w + 32] = b; }
    __syncthreads();
    if (w == 0) {
        a = (l < nw) ? sm[l] : 0.f;
        b = (l < nw) ? sm[l + 32] : 0.f;
        #pragma unroll
        for (int o = 16; o; o >>= 1) {
            a += __shfl_down_sync(0xffffffffu, a, o);
            b += __shfl_down_sync(0xffffffffu, b, o);
        }
    }
}

// ---------------- K1: LN1 on concat(x1,x2,x3); also zero routing counters ---
__global__ void __launch_bounds__(256) k_ln1(
    const float* __restrict__ x1, const float* __restrict__ x2,
    const float* __restrict__ x3,
    const float* __restrict__ w, const float* __restrict__ b)
{
    int t = blockIdx.x, tid = threadIdx.x;
    if (t == 0 && tid < NEXP) g_cnt[tid] = 0;
    int bb = t / NTOT, pos = t % NTOT;
    const float* src = (pos < NCHUNK) ? x1 : (pos < 2 * NCHUNK) ? x2 : x3;
    const float* row = src + ((size_t)bb * NCHUNK + (pos % NCHUNK)) * DMODEL;
    float v0 = row[tid], v1 = row[tid + 256];
    float s = v0 + v1, ss = v0 * v0 + v1 * v1;
    __shared__ float red[64];
    blockReduce2(s, ss, red);
    __shared__ float mu, rstd;
    if (tid == 0) {
        float m = s * (1.f / 512.f);
        float var = ss * (1.f / 512.f) - m * m;
        mu = m; rstd = rsqrtf(var + 1e-5f);
    }
    __syncthreads();
    float* dst = g_h + (size_t)t * DMODEL;
    dst[tid]       = (v0 - mu) * rstd * w[tid]       + b[tid];
    dst[tid + 256] = (v1 - mu) * rstd * w[tid + 256] + b[tid + 256];
}

// ---------------- shared 128x128x8 fp32 GEMM mainloop -----------------------
__device__ __forceinline__ void gemm_main(
    const float* __restrict__ A, int lda, const int* __restrict__ arow_s,
    const float* __restrict__ B, int ldb, int Kdim,
    float (&acc)[8][8], float* As, float* Bs)
{
    const int tid = threadIdx.x;
    const int lr  = tid >> 1;
    const int lk4 = (tid & 1) * 4;
    const int bk  = tid >> 5;
    const int bc4 = (tid & 31) * 4;
    const int ty  = tid >> 4, tx = tid & 15;
    const int ar  = arow_s[lr];
    const float* Aptr = (ar >= 0) ? (A + (size_t)ar * lda + lk4) : A;
    const bool avalid = (ar >= 0);

    for (int k0 = 0; k0 < Kdim; k0 += 8) {
        float4 av = make_float4(0.f, 0.f, 0.f, 0.f);
        if (avalid) av = *(const float4*)(Aptr + k0);
        float4 bv = *(const float4*)(B + (size_t)(k0 + bk) * ldb + bc4);
        As[(lk4 + 0) * 128 + lr] = av.x;
        As[(lk4 + 1) * 128 + lr] = av.y;
        As[(lk4 + 2) * 128 + lr] = av.z;
        As[(lk4 + 3) * 128 + lr] = av.w;
        *(float4*)(Bs + bk * 128 + bc4) = bv;
        __syncthreads();
        #pragma unroll
        for (int kk = 0; kk < 8; kk++) {
            float a0[4], a1[4], b0[4], b1[4];
            *(float4*)a0 = *(const float4*)(As + kk * 128 + ty * 8);
            *(float4*)a1 = *(const float4*)(As + kk * 128 + ty * 8 + 4);
            *(float4*)b0 = *(const float4*)(Bs + kk * 128 + tx * 8);
            *(float4*)b1 = *(const float4*)(Bs + kk * 128 + tx * 8 + 4);
            #pragma unroll
            for (int i = 0; i < 4; i++) {
                #pragma unroll
                for (int j = 0; j < 4; j++) {
                    acc[i][j]         += a0[i] * b0[j];
                    acc[i][j + 4]     += a0[i] * b1[j];
                    acc[i + 4][j]     += a1[i] * b0[j];
                    acc[i + 4][j + 4] += a1[i] * b1[j];
                }
            }
        }
        __syncthreads();
    }
}

// ---------------- K2: QKV GEMM (h @ [q_w | kv_w]) ---------------------------
__global__ void __launch_bounds__(256) k_qkv(
    const float* __restrict__ qw, const float* __restrict__ kvw)
{
    __shared__ float As[8 * 128], Bs[8 * 128];
    __shared__ int arow[128];
    int bx = blockIdx.x;  // 0..11 (col tile of 1536)
    int by = blockIdx.y;  // 0..47
    int tid = threadIdx.x;
    if (tid < 128) arow[tid] = by * 128 + tid;
    __syncthreads();

    const float* B; int ldb, c0;
    if (bx < 4) { B = qw;  ldb = 512;  c0 = bx * 128; }
    else        { B = kvw; ldb = 1024; c0 = bx * 128 - 512; }

    float acc[8][8] = {};
    gemm_main(g_h, DMODEL, arow, B + c0, ldb, DMODEL, acc, As, Bs);

    int ty = tid >> 4, tx = tid & 15;
    #pragma unroll
    for (int i = 0; i < 8; i++) {
        int gr = by * 128 + ty * 8 + i;
        int bb = gr / NTOT, n = gr % NTOT;
        #pragma unroll
        for (int j = 0; j < 8; j++) {
            int gc = bx * 128 + tx * 8 + j;      // 0..1535
            int which = gc >> 9;                 // 0:q 1:k 2:v
            int cc = gc & 511;
            int h = cc >> 6, hd = cc & 63;
            float* dst = (which == 0) ? g_q : (which == 1) ? g_k : g_v;
            dst[(((size_t)bb * NHEADS + h) * NTOT + n) * HDIM + hd] = acc[i][j];
        }
    }
}

// ---------------- K3: attention (flash-style, 1 query row / thread) ---------
__global__ void __launch_bounds__(128) k_attn()
{
    int bh = blockIdx.x;                       // 64
    int n  = blockIdx.y * 128 + threadIdx.x;   // query row
    const float* qp = g_q + ((size_t)bh * NTOT + n) * HDIM;
    float q[HDIM];
    #pragma unroll
    for (int i = 0; i < HDIM; i += 4) {
        float4 t4 = *(const float4*)(qp + i);
        q[i] = t4.x * 0.125f; q[i+1] = t4.y * 0.125f;
        q[i+2] = t4.z * 0.125f; q[i+3] = t4.w * 0.125f;
    }
    float acc[HDIM];
    #pragma unroll
    for (int i = 0; i < HDIM; i++) acc[i] = 0.f;
    float m = -1e30f, l = 0.f;

    __shared__ float Ks[32 * 64], Vs[32 * 64];
    const float* kb = g_k + (size_t)bh * NTOT * HDIM;
    const float* vb = g_v + (size_t)bh * NTOT * HDIM;

    for (int c = 0; c < NTOT; c += 32) {
        __syncthreads();
        #pragma unroll
        for (int i = threadIdx.x; i < 512; i += 128) {
            *(float4*)(Ks + i * 4) = *(const float4*)(kb + c * 64 + i * 4);
            *(float4*)(Vs + i * 4) = *(const float4*)(vb + c * 64 + i * 4);
        }
        __syncthreads();

        float s[32];
        #pragma unroll
        for (int j = 0; j < 32; j++) {
            float d0 = 0.f;
            #pragma unroll
            for (int d = 0; d < 64; d += 4) {
                float4 kk = *(const float4*)(Ks + j * 64 + d);
                d0 += q[d] * kk.x + q[d+1] * kk.y + q[d+2] * kk.z + q[d+3] * kk.w;
            }
            s[j] = d0;
        }
        float cm = s[0];
        #pragma unroll
        for (int j = 1; j < 32; j++) cm = fmaxf(cm, s[j]);
        float mn = fmaxf(m, cm);
        float f = __expf(m - mn);
        m = mn;
        l *= f;
        #pragma unroll
        for (int d = 0; d < 64; d++) acc[d] *= f;
        #pragma unroll
        for (int j = 0; j < 32; j++) {
            float p = __expf(s[j] - m);
            l += p;
            #pragma unroll
            for (int d = 0; d < 64; d += 4) {
                float4 vv = *(const float4*)(Vs + j * 64 + d);
                acc[d]   += p * vv.x; acc[d+1] += p * vv.y;
                acc[d+2] += p * vv.z; acc[d+3] += p * vv.w;
            }
        }
    }
    float inv = 1.f / l;
    int bb = bh >> 3, h = bh & 7;
    float* op = g_o + ((size_t)bb * NTOT + n) * DMODEL + h * HDIM;
    #pragma unroll
    for (int d = 0; d < 64; d++) op[d] = acc[d] * inv;
}

// ---------------- K4: proj GEMM, x2 = 2*(o @ proj_w + proj_b) ---------------
__global__ void __launch_bounds__(256) k_proj(
    const float* __restrict__ pw, const float* __restrict__ pb)
{
    __shared__ float As[8 * 128], Bs[8 * 128];
    __shared__ int arow[128];
    int bx = blockIdx.x, by = blockIdx.y;
    int tid = threadIdx.x;
    if (tid < 128) arow[tid] = by * 128 + tid;
    __syncthreads();

    float acc[8][8] = {};
    gemm_main(g_o, DMODEL, arow, pw + bx * 128, DMODEL, DMODEL, acc, As, Bs);

    int ty = tid >> 4, tx = tid & 15;
    #pragma unroll
    for (int i = 0; i < 8; i++) {
        int gr = by * 128 + ty * 8 + i;
        #pragma unroll
        for (int j = 0; j < 8; j++) {
            int gc = bx * 128 + tx * 8 + j;
            g_x2[(size_t)gr * DMODEL + gc] = 2.f * (acc[i][j] + pb[gc]);
        }
    }
}

// ---------------- K5: LN2 + gate softmax + top2 routing ---------------------
__global__ void __launch_bounds__(128) k_gate(
    const float* __restrict__ n2w, const float* __restrict__ n2b,
    const float* __restrict__ gw)
{
    int t = blockIdx.x, tid = threadIdx.x;
    __shared__ float hs[DMODEL];
    __shared__ float red[64];
    const float* xr = g_x2 + (size_t)t * DMODEL;
    float v[4]; float s = 0.f, ss = 0.f;
    #pragma unroll
    for (int i = 0; i < 4; i++) {
        v[i] = xr[tid + i * 128];
        s += v[i]; ss += v[i] * v[i];
    }
    blockReduce2(s, ss, red);
    __shared__ float mu, rstd;
    if (tid == 0) {
        float m = s * (1.f / 512.f);
        mu = m; rstd = rsqrtf(ss * (1.f / 512.f) - m * m + 1e-5f);
    }
    __syncthreads();
    #pragma unroll
    for (int i = 0; i < 4; i++) {
        int d = tid + i * 128;
        float hv = (v[i] - mu) * rstd * n2w[d] + n2b[d];
        hs[d] = hv;
        g_hn[(size_t)t * DMODEL + d] = hv;
    }
    __syncthreads();
    // gate logits: 16 threads per expert
    int e = tid >> 4, ln = tid & 15;
    float p = 0.f;
    for (int d = ln; d < DMODEL; d += 16) p += hs[d] * gw[d * NEXP + e];
    #pragma unroll
    for (int o = 8; o; o >>= 1) p += __shfl_down_sync(0xffffffffu, p, o, 16);
    __shared__ float lg[NEXP];
    if (ln == 0) lg[e] = p;
    __syncthreads();
    if (tid == 0) {
        int i0 = 0; float b0 = lg[0];
        #pragma unroll
        for (int i = 1; i < NEXP; i++) if (lg[i] > b0) { b0 = lg[i]; i0 = i; }
        int i1 = -1; float b1 = -1e30f;
        #pragma unroll
        for (int i = 0; i < NEXP; i++) {
            if (i == i0) continue;
            if (lg[i] > b1) { b1 = lg[i]; i1 = i; }
        }
        float c0 = 1.f / (1.f + __expf(b1 - b0));  // softmax-top2 renormalized
        int p0 = atomicAdd(&g_cnt[i0], 1);
        g_rows[i0 * SLOTS + p0] = t * 2;
        int p1 = atomicAdd(&g_cnt[i1], 1);
        g_rows[i1 * SLOTS + p1] = t * 2 + 1;
        g_conf[t * 2] = c0;
        g_conf[t * 2 + 1] = 1.f - c0;
    }
}

// ---------------- K6: grouped MoE GEMM 1 (hn @ w1, gelu) --------------------
__global__ void __launch_bounds__(256) k_moe1(
    const float* __restrict__ w1, const float* __restrict__ b1)
{
    int e = blockIdx.z, by = blockIdx.y, bx = blockIdx.x;
    int cnt = g_cnt[e];
    if (by * 128 >= cnt) return;
    __shared__ float As[8 * 128], Bs[8 * 128];
    __shared__ int arow[128], ent_s[128];
    int tid = threadIdx.x;
    if (tid < 128) {
        int rr = by * 128 + tid;
        int ent = (rr < cnt) ? g_rows[e * SLOTS + rr] : -1;
        ent_s[tid] = ent;
        arow[tid] = (ent >= 0) ? (ent >> 1) : -1;   // token index into g_hn
    }
    __syncthreads();

    float acc[8][8] = {};
    gemm_main(g_hn, DMODEL, arow,
              w1 + (size_t)e * DMODEL * DFF + bx * 128, DFF, DMODEL, acc, As, Bs);

    int ty = tid >> 4, tx = tid & 15;
    #pragma unroll
    for (int i = 0; i < 8; i++) {
        int ent = ent_s[ty * 8 + i];
        if (ent < 0) continue;
        #pragma unroll
        for (int j = 0; j < 8; j++) {
            int gc = bx * 128 + tx * 8 + j;
            float vv = acc[i][j] + b1[e * DFF + gc];
            vv = 0.5f * vv * (1.f + erff(vv * 0.70710678118654752f));  // exact gelu
            g_hid[(size_t)ent * DFF + gc] = vv;
        }
    }
}

// ---------------- K7: grouped MoE GEMM 2 (hid @ w2, *conf) ------------------
__global__ void __launch_bounds__(256) k_moe2(
    const float* __restrict__ w2, const float* __restrict__ b2)
{
    int e = blockIdx.z, by = blockIdx.y, bx = blockIdx.x;
    int cnt = g_cnt[e];
    if (by * 128 >= cnt) return;
    __shared__ float As[8 * 128], Bs[8 * 128];
    __shared__ int arow[128], ent_s[128];
    int tid = threadIdx.x;
    if (tid < 128) {
        int rr = by * 128 + tid;
        int ent = (rr < cnt) ? g_rows[e * SLOTS + rr] : -1;
        ent_s[tid] = ent;
        arow[tid] = ent;                            // row index into g_hid
    }
    __syncthreads();

    float acc[8][8] = {};
    gemm_main(g_hid, DFF, arow,
              w2 + (size_t)e * DFF * DMODEL + bx * 128, DMODEL, DFF, acc, As, Bs);

    int ty = tid >> 4, tx = tid & 15;
    #pragma unroll
    for (int i = 0; i < 8; i++) {
        int ent = ent_s[ty * 8 + i];
        if (ent < 0) continue;
        float cf = g_conf[ent];
        #pragma unroll
        for (int j = 0; j < 8; j++) {
            int gc = bx * 128 + tx * 8 + j;
            g_comb[(size_t)ent * DMODEL + gc] = cf * (acc[i][j] + b2[e * DMODEL + gc]);
        }
    }
}

// ---------------- K8: residual + LN(ln1) → out ------------------------------
__global__ void __launch_bounds__(256) k_final(
    const float* __restrict__ lw, const float* __restrict__ lb,
    float* __restrict__ out)
{
    int t = blockIdx.x, tid = threadIdx.x;
    const float* xr = g_x2 + (size_t)t * DMODEL;
    const float* c0 = g_comb + (size_t)(t * 2) * DMODEL;
    const float* c1 = g_comb + (size_t)(t * 2 + 1) * DMODEL;
    float v0 = xr[tid]       + c0[tid]       + c1[tid];
    float v1 = xr[tid + 256] + c0[tid + 256] + c1[tid + 256];
    float s = v0 + v1, ss = v0 * v0 + v1 * v1;
    __shared__ float red[64];
    blockReduce2(s, ss, red);
    __shared__ float mu, rstd;
    if (tid == 0) {
        float m = s * (1.f / 512.f);
        mu = m; rstd = rsqrtf(ss * (1.f / 512.f) - m * m + 1e-5f);
    }
    __syncthreads();
    out[(size_t)t * DMODEL + tid]       = (v0 - mu) * rstd * lw[tid]       + lb[tid];
    out[(size_t)t * DMODEL + tid + 256] = (v1 - mu) * rstd * lw[tid + 256] + lb[tid + 256];
}

// ---------------- launch -----------------------------------------------------
extern "C" void kernel_launch(void* const* d_in, const int* in_sizes, int n_in,
                              void* d_out, int out_size)
{
    const float* x1   = (const float*)d_in[0];
    const float* x2   = (const float*)d_in[1];
    const float* x3   = (const float*)d_in[2];
    const float* n1w  = (const float*)d_in[3];
    const float* n1b  = (const float*)d_in[4];
    const float* n2w  = (const float*)d_in[5];
    const float* n2b  = (const float*)d_in[6];
    const float* l1w  = (const float*)d_in[7];
    const float* l1b  = (const float*)d_in[8];
    const float* qw   = (const float*)d_in[9];
    const float* kvw  = (const float*)d_in[10];
    const float* pw   = (const float*)d_in[11];
    const float* pb   = (const float*)d_in[12];
    const float* gw   = (const float*)d_in[13];
    const float* ew1  = (const float*)d_in[14];
    const float* eb1  = (const float*)d_in[15];
    const float* ew2  = (const float*)d_in[16];
    const float* eb2  = (const float*)d_in[17];
    float* out = (float*)d_out;

    k_ln1<<<TOK, 256>>>(x1, x2, x3, n1w, n1b);
    { dim3 g(12, 48); k_qkv<<<g, 256>>>(qw, kvw); }
    { dim3 g(64, 6);  k_attn<<<g, 128>>>(); }
    { dim3 g(4, 48);  k_proj<<<g, 256>>>(pw, pb); }
    k_gate<<<TOK, 128>>>(n2w, n2b, gw);
    { dim3 g(8, 96, 8); k_moe1<<<g, 256>>>(ew1, eb1); }
    { dim3 g(4, 96, 8); k_moe2<<<g, 256>>>(ew2, eb2); }
    k_final<<<TOK, 256>>>(l1w, l1b, out);
}

// round 6
// speedup vs baseline: 1.2352x; 1.2352x over previous
#include <cuda_runtime.h>
#include <math.h>
#include <stdint.h>

// Problem constants
#define DMODEL 512
#define NHEADS 8
#define HDIM   64
#define NEXP   8
#define DFF    1024
#define BATCH  8
#define NCHUNK 256
#define NTOT   768            // 3 * 256
#define TOK    (BATCH * NTOT) // 6144
#define SLOTS  (TOK * 2)      // 12288 routed (token, slot) rows

// ---------------- scratch ----------------------------------------------------
__device__ float g_h  [TOK * DMODEL];    // LN1 output
__device__ float g_q  [TOK * DMODEL];    // [bh][n][hd]
__device__ float g_k  [TOK * DMODEL];
__device__ float g_v  [TOK * DMODEL];
__device__ float g_o  [TOK * DMODEL];    // attn out, [token][h*64+hd]
__device__ float g_x2 [TOK * DMODEL];    // 2*(o@proj + b)
__device__ float g_hn [TOK * DMODEL];    // LN2 output
__device__ float g_hid[SLOTS * DFF];     // gelu(hn @ w1 + b1), by slot entry
__device__ float g_comb[SLOTS * DMODEL]; // conf * (hid @ w2 + b2), by slot entry
__device__ int   g_rows[NEXP * SLOTS];   // per-expert slot-entry lists
__device__ int   g_cnt [NEXP];
__device__ float g_conf[SLOTS];

// ---------------- helpers ----------------------------------------------------
__device__ __forceinline__ void blockReduce2(float& a, float& b, float* sm) {
    #pragma unroll
    for (int o = 16; o; o >>= 1) {
        a += __shfl_down_sync(0xffffffffu, a, o);
        b += __shfl_down_sync(0xffffffffu, b, o);
    }
    int w = threadIdx.x >> 5, l = threadIdx.x & 31;
    int nw = blockDim.x >> 5;
    if (l == 0) { sm[w] = a; sm[w + 32] = b; }
    __syncthreads();
    if (w == 0) {
        a = (l < nw) ? sm[l] : 0.f;
        b = (l < nw) ? sm[l + 32] : 0.f;
        #pragma unroll
        for (int o = 16; o; o >>= 1) {
            a += __shfl_down_sync(0xffffffffu, a, o);
            b += __shfl_down_sync(0xffffffffu, b, o);
        }
    }
}

__device__ __forceinline__ uint32_t f2tf32(float f) {
    uint32_t r;
    asm("cvt.rna.tf32.f32 %0, %1;" : "=r"(r) : "f"(f));
    return r;
}

// split x into hi (tf32) + lo (tf32 of residual); hi+lo ~ 21-bit accurate
__device__ __forceinline__ void split_tf32(float x, uint32_t& hi, uint32_t& lo) {
    uint32_t h = f2tf32(x);
    float r = x - __uint_as_float(h);
    hi = h;
    lo = f2tf32(r);
}

__device__ __forceinline__ void mma_tf32(float* c, const uint32_t* a,
                                         const uint32_t* b) {
    asm volatile(
        "mma.sync.aligned.m16n8k8.row.col.f32.tf32.tf32.f32 "
        "{%0,%1,%2,%3}, {%4,%5,%6,%7}, {%8,%9}, {%0,%1,%2,%3};"
        : "+f"(c[0]), "+f"(c[1]), "+f"(c[2]), "+f"(c[3])
        : "r"(a[0]), "r"(a[1]), "r"(a[2]), "r"(a[3]), "r"(b[0]), "r"(b[1]));
}

// ---------------- K1: LN1 on concat(x1,x2,x3); also zero routing counters ----
__global__ void __launch_bounds__(256) k_ln1(
    const float* __restrict__ x1, const float* __restrict__ x2,
    const float* __restrict__ x3,
    const float* __restrict__ w, const float* __restrict__ b)
{
    int t = blockIdx.x, tid = threadIdx.x;
    if (t == 0 && tid < NEXP) g_cnt[tid] = 0;
    int bb = t / NTOT, pos = t % NTOT;
    const float* src = (pos < NCHUNK) ? x1 : (pos < 2 * NCHUNK) ? x2 : x3;
    const float* row = src + ((size_t)bb * NCHUNK + (pos % NCHUNK)) * DMODEL;
    float v0 = row[tid], v1 = row[tid + 256];
    float s = v0 + v1, ss = v0 * v0 + v1 * v1;
    __shared__ float red[64];
    blockReduce2(s, ss, red);
    __shared__ float mu, rstd;
    if (tid == 0) {
        float m = s * (1.f / 512.f);
        float var = ss * (1.f / 512.f) - m * m;
        mu = m; rstd = rsqrtf(var + 1e-5f);
    }
    __syncthreads();
    float* dst = g_h + (size_t)t * DMODEL;
    dst[tid]       = (v0 - mu) * rstd * w[tid]       + b[tid];
    dst[tid + 256] = (v1 - mu) * rstd * w[tid + 256] + b[tid + 256];
}

// ---------------- 3xTF32 tensor-core 128x128x16 GEMM mainloop ---------------
// Block: 256 threads = 8 warps, warp grid 2(M) x 4(N), warp tile 64x32.
// Each operand split hi/lo; acc += Ah*Bh + Ah*Bl + Al*Bh (fp32-comparable).
#define AP 20   // A smem row stride (16 k + 4 pad)
#define BP 136  // B smem row stride (128 n + 8 pad)

__device__ __forceinline__ void gemm_3xtf32(
    const float* __restrict__ A, int lda, const int* __restrict__ arow_s,
    const float* __restrict__ B, int ldb, int Kdim,
    float (&acc)[4][4][4],
    uint32_t* Ah, uint32_t* Al, uint32_t* Bh, uint32_t* Bl)
{
    const int tid  = threadIdx.x;
    const int warp = tid >> 5, lane = tid & 31;
    const int gid  = lane >> 2, tig = lane & 3;
    const int wm   = (warp & 1) * 64;
    const int wn   = (warp >> 1) * 32;

    for (int k0 = 0; k0 < Kdim; k0 += 16) {
        // A tile 128x16 (rows gathered): 512 float4 loads over 256 threads
        #pragma unroll
        for (int i = 0; i < 2; i++) {
            int e = tid + i * 256;
            int r = e >> 2, c4 = (e & 3) * 4;
            int ar = arow_s[r];
            float4 v = make_float4(0.f, 0.f, 0.f, 0.f);
            if (ar >= 0) v = *(const float4*)(A + (size_t)ar * lda + k0 + c4);
            uint4 uh, ul;
            split_tf32(v.x, uh.x, ul.x); split_tf32(v.y, uh.y, ul.y);
            split_tf32(v.z, uh.z, ul.z); split_tf32(v.w, uh.w, ul.w);
            *(uint4*)(Ah + r * AP + c4) = uh;
            *(uint4*)(Al + r * AP + c4) = ul;
        }
        // B tile 16x128
        #pragma unroll
        for (int i = 0; i < 2; i++) {
            int e = tid + i * 256;
            int r = e >> 5, c4 = (e & 31) * 4;
            float4 v = *(const float4*)(B + (size_t)(k0 + r) * ldb + c4);
            uint4 uh, ul;
            split_tf32(v.x, uh.x, ul.x); split_tf32(v.y, uh.y, ul.y);
            split_tf32(v.z, uh.z, ul.z); split_tf32(v.w, uh.w, ul.w);
            *(uint4*)(Bh + r * BP + c4) = uh;
            *(uint4*)(Bl + r * BP + c4) = ul;
        }
        __syncthreads();
        #pragma unroll
        for (int kk = 0; kk < 2; kk++) {
            uint32_t afh[4][4], afl[4][4], bfh[4][2], bfl[4][2];
            #pragma unroll
            for (int i = 0; i < 4; i++) {
                int off = (wm + i * 16 + gid) * AP + kk * 8 + tig;
                afh[i][0] = Ah[off];            afl[i][0] = Al[off];
                afh[i][1] = Ah[off + 8 * AP];   afl[i][1] = Al[off + 8 * AP];
                afh[i][2] = Ah[off + 4];        afl[i][2] = Al[off + 4];
                afh[i][3] = Ah[off + 8 * AP + 4]; afl[i][3] = Al[off + 8 * AP + 4];
            }
            #pragma unroll
            for (int j = 0; j < 4; j++) {
                int off = (kk * 8 + tig) * BP + wn + j * 8 + gid;
                bfh[j][0] = Bh[off];            bfl[j][0] = Bl[off];
                bfh[j][1] = Bh[off + 4 * BP];   bfl[j][1] = Bl[off + 4 * BP];
            }
            #pragma unroll
            for (int i = 0; i < 4; i++)
                #pragma unroll
                for (int j = 0; j < 4; j++) {
                    mma_tf32(acc[i][j], afl[i], bfh[j]);  // lo*hi
                    mma_tf32(acc[i][j], afh[i], bfl[j]);  // hi*lo
                    mma_tf32(acc[i][j], afh[i], bfh[j]);  // hi*hi
                }
        }
        __syncthreads();
    }
}

// Epilogue fragment coords: rows r0=wm+i*16+gid, r1=r0+8;
// cols c0=wn+j*8+tig*2, c0+1. regs: [0]=(r0,c0) [1]=(r0,c0+1) [2]=(r1,c0) [3]=(r1,c0+1)

// ---------------- K2: QKV GEMM (h @ [q_w | kv_w]) ---------------------------
__global__ void __launch_bounds__(256) k_qkv(
    const float* __restrict__ qw, const float* __restrict__ kvw)
{
    __shared__ uint32_t Ah[128 * AP], Al[128 * AP], Bh[16 * BP], Bl[16 * BP];
    __shared__ int arow[128];
    int bx = blockIdx.x;  // 0..11 (col tile of 1536)
    int by = blockIdx.y;  // 0..47
    int tid = threadIdx.x;
    if (tid < 128) arow[tid] = by * 128 + tid;
    __syncthreads();

    const float* B; int ldb;
    if (bx < 4) { B = qw + bx * 128;            ldb = 512;  }
    else        { B = kvw + (bx * 128 - 512);   ldb = 1024; }

    float acc[4][4][4] = {};
    gemm_3xtf32(g_h, DMODEL, arow, B, ldb, DMODEL, acc, Ah, Al, Bh, Bl);

    int warp = tid >> 5, lane = tid & 31, gid = lane >> 2, tig = lane & 3;
    int wm = (warp & 1) * 64, wn = (warp >> 1) * 32;
    #pragma unroll
    for (int i = 0; i < 4; i++) {
        #pragma unroll
        for (int j = 0; j < 4; j++) {
            #pragma unroll
            for (int rg = 0; rg < 4; rg++) {
                int r = wm + i * 16 + gid + (rg >> 1) * 8;
                int c = wn + j * 8 + tig * 2 + (rg & 1);
                int gr = by * 128 + r;
                int gc = bx * 128 + c;
                int bb = gr / NTOT, n = gr % NTOT;
                int which = gc >> 9;
                int cc = gc & 511;
                int h = cc >> 6, hd = cc & 63;
                float* dst = (which == 0) ? g_q : (which == 1) ? g_k : g_v;
                dst[(((size_t)bb * NHEADS + h) * NTOT + n) * HDIM + hd] = acc[i][j][rg];
            }
        }
    }
}

// ---------------- K3: attention (flash-style, 1 query row / thread) ---------
__global__ void __launch_bounds__(128) k_attn()
{
    int bh = blockIdx.x;                       // 64
    int n  = blockIdx.y * 128 + threadIdx.x;   // query row
    const float* qp = g_q + ((size_t)bh * NTOT + n) * HDIM;
    float q[HDIM];
    #pragma unroll
    for (int i = 0; i < HDIM; i += 4) {
        float4 t4 = *(const float4*)(qp + i);
        q[i] = t4.x * 0.125f; q[i+1] = t4.y * 0.125f;
        q[i+2] = t4.z * 0.125f; q[i+3] = t4.w * 0.125f;
    }
    float acc[HDIM];
    #pragma unroll
    for (int i = 0; i < HDIM; i++) acc[i] = 0.f;
    float m = -1e30f, l = 0.f;

    __shared__ float Ks[32 * 64], Vs[32 * 64];
    const float* kb = g_k + (size_t)bh * NTOT * HDIM;
    const float* vb = g_v + (size_t)bh * NTOT * HDIM;

    for (int c = 0; c < NTOT; c += 32) {
        __syncthreads();
        #pragma unroll
        for (int i = threadIdx.x; i < 512; i += 128) {
            *(float4*)(Ks + i * 4) = *(const float4*)(kb + c * 64 + i * 4);
            *(float4*)(Vs + i * 4) = *(const float4*)(vb + c * 64 + i * 4);
        }
        __syncthreads();

        float s[32];
        #pragma unroll
        for (int j = 0; j < 32; j++) {
            float d0 = 0.f;
            #pragma unroll
            for (int d = 0; d < 64; d += 4) {
                float4 kk = *(const float4*)(Ks + j * 64 + d);
                d0 += q[d] * kk.x + q[d+1] * kk.y + q[d+2] * kk.z + q[d+3] * kk.w;
            }
            s[j] = d0;
        }
        float cm = s[0];
        #pragma unroll
        for (int j = 1; j < 32; j++) cm = fmaxf(cm, s[j]);
        float mn = fmaxf(m, cm);
        float f = __expf(m - mn);
        m = mn;
        l *= f;
        #pragma unroll
        for (int d = 0; d < 64; d++) acc[d] *= f;
        #pragma unroll
        for (int j = 0; j < 32; j++) {
            float p = __expf(s[j] - m);
            l += p;
            #pragma unroll
            for (int d = 0; d < 64; d += 4) {
                float4 vv = *(const float4*)(Vs + j * 64 + d);
                acc[d]   += p * vv.x; acc[d+1] += p * vv.y;
                acc[d+2] += p * vv.z; acc[d+3] += p * vv.w;
            }
        }
    }
    float inv = 1.f / l;
    int bb = bh >> 3, h = bh & 7;
    float* op = g_o + ((size_t)bb * NTOT + n) * DMODEL + h * HDIM;
    #pragma unroll
    for (int d = 0; d < 64; d++) op[d] = acc[d] * inv;
}

// ---------------- K4: proj GEMM, x2 = 2*(o @ proj_w + proj_b) ---------------
__global__ void __launch_bounds__(256) k_proj(
    const float* __restrict__ pw, const float* __restrict__ pb)
{
    __shared__ uint32_t Ah[128 * AP], Al[128 * AP], Bh[16 * BP], Bl[16 * BP];
    __shared__ int arow[128];
    int bx = blockIdx.x, by = blockIdx.y;
    int tid = threadIdx.x;
    if (tid < 128) arow[tid] = by * 128 + tid;
    __syncthreads();

    float acc[4][4][4] = {};
    gemm_3xtf32(g_o, DMODEL, arow, pw + bx * 128, DMODEL, DMODEL, acc, Ah, Al, Bh, Bl);

    int warp = tid >> 5, lane = tid & 31, gid = lane >> 2, tig = lane & 3;
    int wm = (warp & 1) * 64, wn = (warp >> 1) * 32;
    #pragma unroll
    for (int i = 0; i < 4; i++) {
        #pragma unroll
        for (int j = 0; j < 4; j++) {
            #pragma unroll
            for (int rg = 0; rg < 4; rg++) {
                int r = wm + i * 16 + gid + (rg >> 1) * 8;
                int c = wn + j * 8 + tig * 2 + (rg & 1);
                int gr = by * 128 + r;
                int gc = bx * 128 + c;
                g_x2[(size_t)gr * DMODEL + gc] = 2.f * (acc[i][j][rg] + pb[gc]);
            }
        }
    }
}

// ---------------- K5: LN2 + gate softmax + top2 routing ---------------------
__global__ void __launch_bounds__(128) k_gate(
    const float* __restrict__ n2w, const float* __restrict__ n2b,
    const float* __restrict__ gw)
{
    int t = blockIdx.x, tid = threadIdx.x;
    __shared__ float hs[DMODEL];
    __shared__ float red[64];
    const float* xr = g_x2 + (size_t)t * DMODEL;
    float v[4]; float s = 0.f, ss = 0.f;
    #pragma unroll
    for (int i = 0; i < 4; i++) {
        v[i] = xr[tid + i * 128];
        s += v[i]; ss += v[i] * v[i];
    }
    blockReduce2(s, ss, red);
    __shared__ float mu, rstd;
    if (tid == 0) {
        float m = s * (1.f / 512.f);
        mu = m; rstd = rsqrtf(ss * (1.f / 512.f) - m * m + 1e-5f);
    }
    __syncthreads();
    #pragma unroll
    for (int i = 0; i < 4; i++) {
        int d = tid + i * 128;
        float hv = (v[i] - mu) * rstd * n2w[d] + n2b[d];
        hs[d] = hv;
        g_hn[(size_t)t * DMODEL + d] = hv;
    }
    __syncthreads();
    int e = tid >> 4, ln = tid & 15;
    float p = 0.f;
    for (int d = ln; d < DMODEL; d += 16) p += hs[d] * gw[d * NEXP + e];
    #pragma unroll
    for (int o = 8; o; o >>= 1) p += __shfl_down_sync(0xffffffffu, p, o, 16);
    __shared__ float lg[NEXP];
    if (ln == 0) lg[e] = p;
    __syncthreads();
    if (tid == 0) {
        int i0 = 0; float b0 = lg[0];
        #pragma unroll
        for (int i = 1; i < NEXP; i++) if (lg[i] > b0) { b0 = lg[i]; i0 = i; }
        int i1 = -1; float b1 = -1e30f;
        #pragma unroll
        for (int i = 0; i < NEXP; i++) {
            if (i == i0) continue;
            if (lg[i] > b1) { b1 = lg[i]; i1 = i; }
        }
        float c0 = 1.f / (1.f + __expf(b1 - b0));
        int p0 = atomicAdd(&g_cnt[i0], 1);
        g_rows[i0 * SLOTS + p0] = t * 2;
        int p1 = atomicAdd(&g_cnt[i1], 1);
        g_rows[i1 * SLOTS + p1] = t * 2 + 1;
        g_conf[t * 2] = c0;
        g_conf[t * 2 + 1] = 1.f - c0;
    }
}

// ---------------- K6: grouped MoE GEMM 1 (hn @ w1, gelu) --------------------
__global__ void __launch_bounds__(256) k_moe1(
    const float* __restrict__ w1, const float* __restrict__ b1)
{
    int e = blockIdx.z, by = blockIdx.y, bx = blockIdx.x;
    int cnt = g_cnt[e];
    if (by * 128 >= cnt) return;
    __shared__ uint32_t Ah[128 * AP], Al[128 * AP], Bh[16 * BP], Bl[16 * BP];
    __shared__ int arow[128], ent_s[128];
    int tid = threadIdx.x;
    if (tid < 128) {
        int rr = by * 128 + tid;
        int ent = (rr < cnt) ? g_rows[e * SLOTS + rr] : -1;
        ent_s[tid] = ent;
        arow[tid] = (ent >= 0) ? (ent >> 1) : -1;
    }
    __syncthreads();

    float acc[4][4][4] = {};
    gemm_3xtf32(g_hn, DMODEL, arow,
                w1 + (size_t)e * DMODEL * DFF + bx * 128, DFF, DMODEL, acc, Ah, Al, Bh, Bl);

    int warp = tid >> 5, lane = tid & 31, gid = lane >> 2, tig = lane & 3;
    int wm = (warp & 1) * 64, wn = (warp >> 1) * 32;
    #pragma unroll
    for (int i = 0; i < 4; i++) {
        #pragma unroll
        for (int j = 0; j < 4; j++) {
            #pragma unroll
            for (int rg = 0; rg < 4; rg++) {
                int r = wm + i * 16 + gid + (rg >> 1) * 8;
                int ent = ent_s[r];
                if (ent < 0) continue;
                int gc = bx * 128 + wn + j * 8 + tig * 2 + (rg & 1);
                float vv = acc[i][j][rg] + b1[e * DFF + gc];
                vv = 0.5f * vv * (1.f + erff(vv * 0.70710678118654752f));
                g_hid[(size_t)ent * DFF + gc] = vv;
            }
        }
    }
}

// ---------------- K7: grouped MoE GEMM 2 (hid @ w2, *conf) ------------------
__global__ void __launch_bounds__(256) k_moe2(
    const float* __restrict__ w2, const float* __restrict__ b2)
{
    int e = blockIdx.z, by = blockIdx.y, bx = blockIdx.x;
    int cnt = g_cnt[e];
    if (by * 128 >= cnt) return;
    __shared__ uint32_t Ah[128 * AP], Al[128 * AP], Bh[16 * BP], Bl[16 * BP];
    __shared__ int arow[128], ent_s[128];
    int tid = threadIdx.x;
    if (tid < 128) {
        int rr = by * 128 + tid;
        int ent = (rr < cnt) ? g_rows[e * SLOTS + rr] : -1;
        ent_s[tid] = ent;
        arow[tid] = ent;
    }
    __syncthreads();

    float acc[4][4][4] = {};
    gemm_3xtf32(g_hid, DFF, arow,
                w2 + (size_t)e * DFF * DMODEL + bx * 128, DMODEL, DFF, acc, Ah, Al, Bh, Bl);

    int warp = tid >> 5, lane = tid & 31, gid = lane >> 2, tig = lane & 3;
    int wm = (warp & 1) * 64, wn = (warp >> 1) * 32;
    #pragma unroll
    for (int i = 0; i < 4; i++) {
        #pragma unroll
        for (int j = 0; j < 4; j++) {
            #pragma unroll
            for (int rg = 0; rg < 4; rg++) {
                int r = wm + i * 16 + gid + (rg >> 1) * 8;
                int ent = ent_s[r];
                if (ent < 0) continue;
                float cf = g_conf[ent];
                int gc = bx * 128 + wn + j * 8 + tig * 2 + (rg & 1);
                g_comb[(size_t)ent * DMODEL + gc] = cf * (acc[i][j][rg] + b2[e * DMODEL + gc]);
            }
        }
    }
}

// ---------------- K8: residual + LN(ln1) → out ------------------------------
__global__ void __launch_bounds__(256) k_final(
    const float* __restrict__ lw, const float* __restrict__ lb,
    float* __restrict__ out)
{
    int t = blockIdx.x, tid = threadIdx.x;
    const float* xr = g_x2 + (size_t)t * DMODEL;
    const float* c0 = g_comb + (size_t)(t * 2) * DMODEL;
    const float* c1 = g_comb + (size_t)(t * 2 + 1) * DMODEL;
    float v0 = xr[tid]       + c0[tid]       + c1[tid];
    float v1 = xr[tid + 256] + c0[tid + 256] + c1[tid + 256];
    float s = v0 + v1, ss = v0 * v0 + v1 * v1;
    __shared__ float red[64];
    blockReduce2(s, ss, red);
    __shared__ float mu, rstd;
    if (tid == 0) {
        float m = s * (1.f / 512.f);
        mu = m; rstd = rsqrtf(ss * (1.f / 512.f) - m * m + 1e-5f);
    }
    __syncthreads();
    out[(size_t)t * DMODEL + tid]       = (v0 - mu) * rstd * lw[tid]       + lb[tid];
    out[(size_t)t * DMODEL + tid + 256] = (v1 - mu) * rstd * lw[tid + 256] + lb[tid + 256];
}

// ---------------- launch -----------------------------------------------------
extern "C" void kernel_launch(void* const* d_in, const int* in_sizes, int n_in,
                              void* d_out, int out_size)
{
    const float* x1   = (const float*)d_in[0];
    const float* x2   = (const float*)d_in[1];
    const float* x3   = (const float*)d_in[2];
    const float* n1w  = (const float*)d_in[3];
    const float* n1b  = (const float*)d_in[4];
    const float* n2w  = (const float*)d_in[5];
    const float* n2b  = (const float*)d_in[6];
    const float* l1w  = (const float*)d_in[7];
    const float* l1b  = (const float*)d_in[8];
    const float* qw   = (const float*)d_in[9];
    const float* kvw  = (const float*)d_in[10];
    const float* pw   = (const float*)d_in[11];
    const float* pb   = (const float*)d_in[12];
    const float* gw   = (const float*)d_in[13];
    const float* ew1  = (const float*)d_in[14];
    const float* eb1  = (const float*)d_in[15];
    const float* ew2  = (const float*)d_in[16];
    const float* eb2  = (const float*)d_in[17];
    float* out = (float*)d_out;

    k_ln1<<<TOK, 256>>>(x1, x2, x3, n1w, n1b);
    { dim3 g(12, 48); k_qkv<<<g, 256>>>(qw, kvw); }
    { dim3 g(64, 6);  k_attn<<<g, 128>>>(); }
    { dim3 g(4, 48);  k_proj<<<g, 256>>>(pw, pb); }
    k_gate<<<TOK, 128>>>(n2w, n2b, gw);
    { dim3 g(8, 96, 8); k_moe1<<<g, 256>>>(ew1, eb1); }
    { dim3 g(4, 96, 8); k_moe2<<<g, 256>>>(ew2, eb2); }
    k_final<<<TOK, 256>>>(l1w, l1b, out);
}

// round 7
// speedup vs baseline: 1.3223x; 1.0705x over previous
#include <cuda_runtime.h>
#include <math.h>
#include <stdint.h>

// Problem constants
#define DMODEL 512
#define NHEADS 8
#define HDIM   64
#define NEXP   8
#define DFF    1024
#define BATCH  8
#define NCHUNK 256
#define NTOT   768            // 3 * 256
#define TOK    (BATCH * NTOT) // 6144
#define SLOTS  (TOK * 2)      // 12288 routed (token, slot) rows

// ---------------- scratch ----------------------------------------------------
__device__ float g_h  [TOK * DMODEL];    // LN1 output
__device__ float g_q  [TOK * DMODEL];    // [bh][n][hd]
__device__ float g_k  [TOK * DMODEL];
__device__ float g_v  [TOK * DMODEL];
__device__ float g_o  [TOK * DMODEL];    // attn out, [token][h*64+hd]
__device__ float g_x2 [TOK * DMODEL];    // 2*(o@proj + b)
__device__ float g_hn [TOK * DMODEL];    // LN2 output
__device__ float g_hid[SLOTS * DFF];     // gelu(hn @ w1 + b1), by slot entry
__device__ float g_comb[SLOTS * DMODEL]; // conf * (hid @ w2 + b2), by slot entry
__device__ int   g_rows[NEXP * SLOTS];   // per-expert slot-entry lists
__device__ int   g_cnt [NEXP];
__device__ float g_conf[SLOTS];

// ---------------- helpers ----------------------------------------------------
__device__ __forceinline__ void blockReduce2(float& a, float& b, float* sm) {
    #pragma unroll
    for (int o = 16; o; o >>= 1) {
        a += __shfl_down_sync(0xffffffffu, a, o);
        b += __shfl_down_sync(0xffffffffu, b, o);
    }
    int w = threadIdx.x >> 5, l = threadIdx.x & 31;
    int nw = blockDim.x >> 5;
    if (l == 0) { sm[w] = a; sm[w + 32] = b; }
    __syncthreads();
    if (w == 0) {
        a = (l < nw) ? sm[l] : 0.f;
        b = (l < nw) ? sm[l + 32] : 0.f;
        #pragma unroll
        for (int o = 16; o; o >>= 1) {
            a += __shfl_down_sync(0xffffffffu, a, o);
            b += __shfl_down_sync(0xffffffffu, b, o);
        }
    }
}

__device__ __forceinline__ uint32_t f2tf32(float f) {
    uint32_t r;
    asm("cvt.rna.tf32.f32 %0, %1;" : "=r"(r) : "f"(f));
    return r;
}

// split x into hi (tf32) + lo (tf32 of residual); hi+lo ~ 21-bit accurate
__device__ __forceinline__ void split_tf32(float x, uint32_t& hi, uint32_t& lo) {
    uint32_t h = f2tf32(x);
    float r = x - __uint_as_float(h);
    hi = h;
    lo = f2tf32(r);
}

__device__ __forceinline__ void mma_tf32(float* c, const uint32_t* a,
                                         const uint32_t* b) {
    asm volatile(
        "mma.sync.aligned.m16n8k8.row.col.f32.tf32.tf32.f32 "
        "{%0,%1,%2,%3}, {%4,%5,%6,%7}, {%8,%9}, {%0,%1,%2,%3};"
        : "+f"(c[0]), "+f"(c[1]), "+f"(c[2]), "+f"(c[3])
        : "r"(a[0]), "r"(a[1]), "r"(a[2]), "r"(a[3]), "r"(b[0]), "r"(b[1]));
}

// 16B async copy, zero-fill when !valid
__device__ __forceinline__ void cp_async16(float* dst, const float* src, bool valid) {
    uint32_t d = (uint32_t)__cvta_generic_to_shared(dst);
    int sz = valid ? 16 : 0;
    asm volatile("cp.async.cg.shared.global [%0], [%1], 16, %2;\n"
                 :: "r"(d), "l"(src), "r"(sz));
}
__device__ __forceinline__ void cp_commit() {
    asm volatile("cp.async.commit_group;\n");
}
template <int N>
__device__ __forceinline__ void cp_wait() {
    asm volatile("cp.async.wait_group %0;\n" :: "n"(N));
}

// ---------------- K1: LN1 on concat(x1,x2,x3); also zero routing counters ----
__global__ void __launch_bounds__(256) k_ln1(
    const float* __restrict__ x1, const float* __restrict__ x2,
    const float* __restrict__ x3,
    const float* __restrict__ w, const float* __restrict__ b)
{
    int t = blockIdx.x, tid = threadIdx.x;
    if (t == 0 && tid < NEXP) g_cnt[tid] = 0;
    int bb = t / NTOT, pos = t % NTOT;
    const float* src = (pos < NCHUNK) ? x1 : (pos < 2 * NCHUNK) ? x2 : x3;
    const float* row = src + ((size_t)bb * NCHUNK + (pos % NCHUNK)) * DMODEL;
    float v0 = row[tid], v1 = row[tid + 256];
    float s = v0 + v1, ss = v0 * v0 + v1 * v1;
    __shared__ float red[64];
    blockReduce2(s, ss, red);
    __shared__ float mu, rstd;
    if (tid == 0) {
        float m = s * (1.f / 512.f);
        float var = ss * (1.f / 512.f) - m * m;
        mu = m; rstd = rsqrtf(var + 1e-5f);
    }
    __syncthreads();
    float* dst = g_h + (size_t)t * DMODEL;
    dst[tid]       = (v0 - mu) * rstd * w[tid]       + b[tid];
    dst[tid + 256] = (v1 - mu) * rstd * w[tid + 256] + b[tid + 256];
}

// ---------------- 3xTF32 pipelined 128x128x16 GEMM mainloop -----------------
// 256 threads = 8 warps, warp grid 2(M) x 4(N), warp tile 64x32.
// fp32 tiles double-buffered via cp.async; hi/lo split in consumer registers.
// acc += Ah*Bh + Ah*Bl + Al*Bh (fp32-comparable precision).
#define AP 20            // A smem row stride (16 k + 4 pad) — 80B, 16B-aligned
#define BP 136           // B smem row stride (128 n + 8 pad) — 544B, 16B-aligned
#define A_SZ (128 * AP)
#define B_SZ (16 * BP)

__device__ __forceinline__ void gemm_3xtf32(
    const float* __restrict__ A, int lda, const int* __restrict__ arow_s,
    const float* __restrict__ B, int ldb, int Kdim,
    float (&acc)[4][4][4], float* As, float* Bs)
{
    const int tid  = threadIdx.x;
    const int warp = tid >> 5, lane = tid & 31;
    const int gid  = lane >> 2, tig = lane & 3;
    const int wm   = (warp & 1) * 64;
    const int wn   = (warp >> 1) * 32;

    // producer thread's fixed coordinates
    const int ar0 = tid >> 2,  ac0 = (tid & 3) * 4;          // A elems 0,1
    const int ar1 = (tid + 256) >> 2, ac1 = ac0;             // (e&3) same
    const int br0 = tid >> 5,  bc0 = (tid & 31) * 4;
    const int br1 = (tid + 256) >> 5, bc1 = bc0;
    const int ga0 = arow_s[ar0], ga1 = arow_s[ar1];

    auto load_tile = [&](int k0, int buf) {
        float* Ad = As + buf * A_SZ;
        float* Bd = Bs + buf * B_SZ;
        cp_async16(Ad + ar0 * AP + ac0,
                   A + (size_t)(ga0 < 0 ? 0 : ga0) * lda + k0 + ac0, ga0 >= 0);
        cp_async16(Ad + ar1 * AP + ac1,
                   A + (size_t)(ga1 < 0 ? 0 : ga1) * lda + k0 + ac1, ga1 >= 0);
        cp_async16(Bd + br0 * BP + bc0, B + (size_t)(k0 + br0) * ldb + bc0, true);
        cp_async16(Bd + br1 * BP + bc1, B + (size_t)(k0 + br1) * ldb + bc1, true);
    };

    const int nk = Kdim >> 4;
    load_tile(0, 0);
    cp_commit();

    for (int it = 0; it < nk; it++) {
        if (it + 1 < nk) load_tile((it + 1) << 4, (it + 1) & 1);
        cp_commit();
        cp_wait<1>();
        __syncthreads();

        const float* Af = As + (it & 1) * A_SZ;
        const float* Bf = Bs + (it & 1) * B_SZ;
        #pragma unroll
        for (int kk = 0; kk < 2; kk++) {
            uint32_t afh[4][4], afl[4][4], bfh[4][2], bfl[4][2];
            #pragma unroll
            for (int i = 0; i < 4; i++) {
                int off = (wm + i * 16 + gid) * AP + kk * 8 + tig;
                split_tf32(Af[off],              afh[i][0], afl[i][0]);
                split_tf32(Af[off + 8 * AP],     afh[i][1], afl[i][1]);
                split_tf32(Af[off + 4],          afh[i][2], afl[i][2]);
                split_tf32(Af[off + 8 * AP + 4], afh[i][3], afl[i][3]);
            }
            #pragma unroll
            for (int j = 0; j < 4; j++) {
                int off = (kk * 8 + tig) * BP + wn + j * 8 + gid;
                split_tf32(Bf[off],          bfh[j][0], bfl[j][0]);
                split_tf32(Bf[off + 4 * BP], bfh[j][1], bfl[j][1]);
            }
            #pragma unroll
            for (int i = 0; i < 4; i++)
                #pragma unroll
                for (int j = 0; j < 4; j++) {
                    mma_tf32(acc[i][j], afl[i], bfh[j]);  // lo*hi
                    mma_tf32(acc[i][j], afh[i], bfl[j]);  // hi*lo
                    mma_tf32(acc[i][j], afh[i], bfh[j]);  // hi*hi
                }
        }
        __syncthreads();
    }
}

// Epilogue fragment coords: rows r0=wm+i*16+gid, r1=r0+8;
// cols c0=wn+j*8+tig*2, c0+1. regs: [0]=(r0,c0) [1]=(r0,c0+1) [2]=(r1,c0) [3]=(r1,c0+1)

// ---------------- K2: QKV GEMM (h @ [q_w | kv_w]) ---------------------------
__global__ void __launch_bounds__(256) k_qkv(
    const float* __restrict__ qw, const float* __restrict__ kvw)
{
    __shared__ float As[2 * A_SZ], Bs[2 * B_SZ];
    __shared__ int arow[128];
    int bx = blockIdx.x;  // 0..11 (col tile of 1536)
    int by = blockIdx.y;  // 0..47
    int tid = threadIdx.x;
    if (tid < 128) arow[tid] = by * 128 + tid;
    __syncthreads();

    const float* B; int ldb;
    if (bx < 4) { B = qw + bx * 128;            ldb = 512;  }
    else        { B = kvw + (bx * 128 - 512);   ldb = 1024; }

    float acc[4][4][4] = {};
    gemm_3xtf32(g_h, DMODEL, arow, B, ldb, DMODEL, acc, As, Bs);

    int warp = tid >> 5, lane = tid & 31, gid = lane >> 2, tig = lane & 3;
    int wm = (warp & 1) * 64, wn = (warp >> 1) * 32;
    #pragma unroll
    for (int i = 0; i < 4; i++) {
        #pragma unroll
        for (int j = 0; j < 4; j++) {
            #pragma unroll
            for (int rg = 0; rg < 4; rg++) {
                int r = wm + i * 16 + gid + (rg >> 1) * 8;
                int c = wn + j * 8 + tig * 2 + (rg & 1);
                int gr = by * 128 + r;
                int gc = bx * 128 + c;
                int bb = gr / NTOT, n = gr % NTOT;
                int which = gc >> 9;
                int cc = gc & 511;
                int h = cc >> 6, hd = cc & 63;
                float* dst = (which == 0) ? g_q : (which == 1) ? g_k : g_v;
                dst[(((size_t)bb * NHEADS + h) * NTOT + n) * HDIM + hd] = acc[i][j][rg];
            }
        }
    }
}

// ---------------- K3: attention (flash-style, 1 query row / thread) ---------
__global__ void __launch_bounds__(128) k_attn()
{
    int bh = blockIdx.x;                       // 64
    int n  = blockIdx.y * 128 + threadIdx.x;   // query row
    const float* qp = g_q + ((size_t)bh * NTOT + n) * HDIM;
    float q[HDIM];
    #pragma unroll
    for (int i = 0; i < HDIM; i += 4) {
        float4 t4 = *(const float4*)(qp + i);
        q[i] = t4.x * 0.125f; q[i+1] = t4.y * 0.125f;
        q[i+2] = t4.z * 0.125f; q[i+3] = t4.w * 0.125f;
    }
    float acc[HDIM];
    #pragma unroll
    for (int i = 0; i < HDIM; i++) acc[i] = 0.f;
    float m = -1e30f, l = 0.f;

    __shared__ float Ks[32 * 64], Vs[32 * 64];
    const float* kb = g_k + (size_t)bh * NTOT * HDIM;
    const float* vb = g_v + (size_t)bh * NTOT * HDIM;

    for (int c = 0; c < NTOT; c += 32) {
        __syncthreads();
        #pragma unroll
        for (int i = threadIdx.x; i < 512; i += 128) {
            *(float4*)(Ks + i * 4) = *(const float4*)(kb + c * 64 + i * 4);
            *(float4*)(Vs + i * 4) = *(const float4*)(vb + c * 64 + i * 4);
        }
        __syncthreads();

        float s[32];
        #pragma unroll
        for (int j = 0; j < 32; j++) {
            float d0 = 0.f;
            #pragma unroll
            for (int d = 0; d < 64; d += 4) {
                float4 kk = *(const float4*)(Ks + j * 64 + d);
                d0 += q[d] * kk.x + q[d+1] * kk.y + q[d+2] * kk.z + q[d+3] * kk.w;
            }
            s[j] = d0;
        }
        float cm = s[0];
        #pragma unroll
        for (int j = 1; j < 32; j++) cm = fmaxf(cm, s[j]);
        float mn = fmaxf(m, cm);
        float f = __expf(m - mn);
        m = mn;
        l *= f;
        #pragma unroll
        for (int d = 0; d < 64; d++) acc[d] *= f;
        #pragma unroll
        for (int j = 0; j < 32; j++) {
            float p = __expf(s[j] - m);
            l += p;
            #pragma unroll
            for (int d = 0; d < 64; d += 4) {
                float4 vv = *(const float4*)(Vs + j * 64 + d);
                acc[d]   += p * vv.x; acc[d+1] += p * vv.y;
                acc[d+2] += p * vv.z; acc[d+3] += p * vv.w;
            }
        }
    }
    float inv = 1.f / l;
    int bb = bh >> 3, h = bh & 7;
    float* op = g_o + ((size_t)bb * NTOT + n) * DMODEL + h * HDIM;
    #pragma unroll
    for (int d = 0; d < 64; d++) op[d] = acc[d] * inv;
}

// ---------------- K4: proj GEMM, x2 = 2*(o @ proj_w + proj_b) ---------------
__global__ void __launch_bounds__(256) k_proj(
    const float* __restrict__ pw, const float* __restrict__ pb)
{
    __shared__ float As[2 * A_SZ], Bs[2 * B_SZ];
    __shared__ int arow[128];
    int bx = blockIdx.x, by = blockIdx.y;
    int tid = threadIdx.x;
    if (tid < 128) arow[tid] = by * 128 + tid;
    __syncthreads();

    float acc[4][4][4] = {};
    gemm_3xtf32(g_o, DMODEL, arow, pw + bx * 128, DMODEL, DMODEL, acc, As, Bs);

    int warp = tid >> 5, lane = tid & 31, gid = lane >> 2, tig = lane & 3;
    int wm = (warp & 1) * 64, wn = (warp >> 1) * 32;
    #pragma unroll
    for (int i = 0; i < 4; i++) {
        #pragma unroll
        for (int j = 0; j < 4; j++) {
            #pragma unroll
            for (int rg = 0; rg < 4; rg++) {
                int r = wm + i * 16 + gid + (rg >> 1) * 8;
                int c = wn + j * 8 + tig * 2 + (rg & 1);
                int gr = by * 128 + r;
                int gc = bx * 128 + c;
                g_x2[(size_t)gr * DMODEL + gc] = 2.f * (acc[i][j][rg] + pb[gc]);
            }
        }
    }
}

// ---------------- K5: LN2 + gate softmax + top2 routing ---------------------
__global__ void __launch_bounds__(128) k_gate(
    const float* __restrict__ n2w, const float* __restrict__ n2b,
    const float* __restrict__ gw)
{
    int t = blockIdx.x, tid = threadIdx.x;
    __shared__ float hs[DMODEL];
    __shared__ float red[64];
    const float* xr = g_x2 + (size_t)t * DMODEL;
    float v[4]; float s = 0.f, ss = 0.f;
    #pragma unroll
    for (int i = 0; i < 4; i++) {
        v[i] = xr[tid + i * 128];
        s += v[i]; ss += v[i] * v[i];
    }
    blockReduce2(s, ss, red);
    __shared__ float mu, rstd;
    if (tid == 0) {
        float m = s * (1.f / 512.f);
        mu = m; rstd = rsqrtf(ss * (1.f / 512.f) - m * m + 1e-5f);
    }
    __syncthreads();
    #pragma unroll
    for (int i = 0; i < 4; i++) {
        int d = tid + i * 128;
        float hv = (v[i] - mu) * rstd * n2w[d] + n2b[d];
        hs[d] = hv;
        g_hn[(size_t)t * DMODEL + d] = hv;
    }
    __syncthreads();
    int e = tid >> 4, ln = tid & 15;
    float p = 0.f;
    for (int d = ln; d < DMODEL; d += 16) p += hs[d] * gw[d * NEXP + e];
    #pragma unroll
    for (int o = 8; o; o >>= 1) p += __shfl_down_sync(0xffffffffu, p, o, 16);
    __shared__ float lg[NEXP];
    if (ln == 0) lg[e] = p;
    __syncthreads();
    if (tid == 0) {
        int i0 = 0; float b0 = lg[0];
        #pragma unroll
        for (int i = 1; i < NEXP; i++) if (lg[i] > b0) { b0 = lg[i]; i0 = i; }
        int i1 = -1; float b1 = -1e30f;
        #pragma unroll
        for (int i = 0; i < NEXP; i++) {
            if (i == i0) continue;
            if (lg[i] > b1) { b1 = lg[i]; i1 = i; }
        }
        float c0 = 1.f / (1.f + __expf(b1 - b0));
        int p0 = atomicAdd(&g_cnt[i0], 1);
        g_rows[i0 * SLOTS + p0] = t * 2;
        int p1 = atomicAdd(&g_cnt[i1], 1);
        g_rows[i1 * SLOTS + p1] = t * 2 + 1;
        g_conf[t * 2] = c0;
        g_conf[t * 2 + 1] = 1.f - c0;
    }
}

// ---------------- K6: grouped MoE GEMM 1 (hn @ w1, gelu) --------------------
__global__ void __launch_bounds__(256) k_moe1(
    const float* __restrict__ w1, const float* __restrict__ b1)
{
    int e = blockIdx.z, by = blockIdx.y, bx = blockIdx.x;
    int cnt = g_cnt[e];
    if (by * 128 >= cnt) return;
    __shared__ float As[2 * A_SZ], Bs[2 * B_SZ];
    __shared__ int arow[128], ent_s[128];
    int tid = threadIdx.x;
    if (tid < 128) {
        int rr = by * 128 + tid;
        int ent = (rr < cnt) ? g_rows[e * SLOTS + rr] : -1;
        ent_s[tid] = ent;
        arow[tid] = (ent >= 0) ? (ent >> 1) : -1;
    }
    __syncthreads();

    float acc[4][4][4] = {};
    gemm_3xtf32(g_hn, DMODEL, arow,
                w1 + (size_t)e * DMODEL * DFF + bx * 128, DFF, DMODEL, acc, As, Bs);

    int warp = tid >> 5, lane = tid & 31, gid = lane >> 2, tig = lane & 3;
    int wm = (warp & 1) * 64, wn = (warp >> 1) * 32;
    #pragma unroll
    for (int i = 0; i < 4; i++) {
        #pragma unroll
        for (int j = 0; j < 4; j++) {
            #pragma unroll
            for (int rg = 0; rg < 4; rg++) {
                int r = wm + i * 16 + gid + (rg >> 1) * 8;
                int ent = ent_s[r];
                if (ent < 0) continue;
                int gc = bx * 128 + wn + j * 8 + tig * 2 + (rg & 1);
                float vv = acc[i][j][rg] + b1[e * DFF + gc];
                vv = 0.5f * vv * (1.f + erff(vv * 0.70710678118654752f));
                g_hid[(size_t)ent * DFF + gc] = vv;
            }
        }
    }
}

// ---------------- K7: grouped MoE GEMM 2 (hid @ w2, *conf) ------------------
__global__ void __launch_bounds__(256) k_moe2(
    const float* __restrict__ w2, const float* __restrict__ b2)
{
    int e = blockIdx.z, by = blockIdx.y, bx = blockIdx.x;
    int cnt = g_cnt[e];
    if (by * 128 >= cnt) return;
    __shared__ float As[2 * A_SZ], Bs[2 * B_SZ];
    __shared__ int arow[128], ent_s[128];
    int tid = threadIdx.x;
    if (tid < 128) {
        int rr = by * 128 + tid;
        int ent = (rr < cnt) ? g_rows[e * SLOTS + rr] : -1;
        ent_s[tid] = ent;
        arow[tid] = ent;
    }
    __syncthreads();

    float acc[4][4][4] = {};
    gemm_3xtf32(g_hid, DFF, arow,
                w2 + (size_t)e * DFF * DMODEL + bx * 128, DMODEL, DFF, acc, As, Bs);

    int warp = tid >> 5, lane = tid & 31, gid = lane >> 2, tig = lane & 3;
    int wm = (warp & 1) * 64, wn = (warp >> 1) * 32;
    #pragma unroll
    for (int i = 0; i < 4; i++) {
        #pragma unroll
        for (int j = 0; j < 4; j++) {
            #pragma unroll
            for (int rg = 0; rg < 4; rg++) {
                int r = wm + i * 16 + gid + (rg >> 1) * 8;
                int ent = ent_s[r];
                if (ent < 0) continue;
                float cf = g_conf[ent];
                int gc = bx * 128 + wn + j * 8 + tig * 2 + (rg & 1);
                g_comb[(size_t)ent * DMODEL + gc] = cf * (acc[i][j][rg] + b2[e * DMODEL + gc]);
            }
        }
    }
}

// ---------------- K8: residual + LN(ln1) → out ------------------------------
__global__ void __launch_bounds__(256) k_final(
    const float* __restrict__ lw, const float* __restrict__ lb,
    float* __restrict__ out)
{
    int t = blockIdx.x, tid = threadIdx.x;
    const float* xr = g_x2 + (size_t)t * DMODEL;
    const float* c0 = g_comb + (size_t)(t * 2) * DMODEL;
    const float* c1 = g_comb + (size_t)(t * 2 + 1) * DMODEL;
    float v0 = xr[tid]       + c0[tid]       + c1[tid];
    float v1 = xr[tid + 256] + c0[tid + 256] + c1[tid + 256];
    float s = v0 + v1, ss = v0 * v0 + v1 * v1;
    __shared__ float red[64];
    blockReduce2(s, ss, red);
    __shared__ float mu, rstd;
    if (tid == 0) {
        float m = s * (1.f / 512.f);
        mu = m; rstd = rsqrtf(ss * (1.f / 512.f) - m * m + 1e-5f);
    }
    __syncthreads();
    out[(size_t)t * DMODEL + tid]       = (v0 - mu) * rstd * lw[tid]       + lb[tid];
    out[(size_t)t * DMODEL + tid + 256] = (v1 - mu) * rstd * lw[tid + 256] + lb[tid + 256];
}

// ---------------- launch -----------------------------------------------------
extern "C" void kernel_launch(void* const* d_in, const int* in_sizes, int n_in,
                              void* d_out, int out_size)
{
    const float* x1   = (const float*)d_in[0];
    const float* x2   = (const float*)d_in[1];
    const float* x3   = (const float*)d_in[2];
    const float* n1w  = (const float*)d_in[3];
    const float* n1b  = (const float*)d_in[4];
    const float* n2w  = (const float*)d_in[5];
    const float* n2b  = (const float*)d_in[6];
    const float* l1w  = (const float*)d_in[7];
    const float* l1b  = (const float*)d_in[8];
    const float* qw   = (const float*)d_in[9];
    const float* kvw  = (const float*)d_in[10];
    const float* pw   = (const float*)d_in[11];
    const float* pb   = (const float*)d_in[12];
    const float* gw   = (const float*)d_in[13];
    const float* ew1  = (const float*)d_in[14];
    const float* eb1  = (const float*)d_in[15];
    const float* ew2  = (const float*)d_in[16];
    const float* eb2  = (const float*)d_in[17];
    float* out = (float*)d_out;

    k_ln1<<<TOK, 256>>>(x1, x2, x3, n1w, n1b);
    { dim3 g(12, 48); k_qkv<<<g, 256>>>(qw, kvw); }
    { dim3 g(64, 6);  k_attn<<<g, 128>>>(); }
    { dim3 g(4, 48);  k_proj<<<g, 256>>>(pw, pb); }
    k_gate<<<TOK, 128>>>(n2w, n2b, gw);
    { dim3 g(8, 96, 8); k_moe1<<<g, 256>>>(ew1, eb1); }
    { dim3 g(4, 96, 8); k_moe2<<<g, 256>>>(ew2, eb2); }
    k_final<<<TOK, 256>>>(l1w, l1b, out);
}